// round 1
// baseline (speedup 1.0000x reference)
#include <cuda_runtime.h>

#define BATCH  8
#define SEQ    2048
#define DMODEL 1024
#define NSTATE 256
#define LCH    16
#define NCHUNK (SEQ / LCH)            // 128
#define MROWS  (BATCH * SEQ)          // 16384
#define TRIM   (LCH * NSTATE)         // 4096
#define NCOLS  (NCHUNK * BATCH)       // 1024
#define Y_ELEMS ((size_t)MROWS * DMODEL)

// Static scratch (no allocations allowed)
__device__ float g_Pow[17 * NSTATE * NSTATE];          // A^0 .. A^16
__device__ float g_U [TRIM * NCOLS];                   // u stacked per chunk: [(k,n)][(i,b)]
__device__ float g_S3[TRIM * NCOLS];                   // intra-chunk partial states
__device__ float g_Hc[TRIM * NCOLS];                   // boundary corrections
__device__ float g_Hs[(size_t)MROWS * NSTATE];         // hs in [(b,t)][n] layout

#define BM 64
#define BN 64
#define BK 16

// ---- shared-memory tile loaders -------------------------------------------
// A tile (BM x BK) from row-major [M x lda], stored transposed As[BK][BM]
#define LOAD_A_ROW(Asrc, lda) do {                                            \
    int lm_ = tid >> 2; int lk_ = (tid & 3) << 2;                             \
    const float4 v_ = *(const float4*)((Asrc) + (size_t)lm_ * (lda) + lk_);   \
    As[lk_+0][lm_] = v_.x; As[lk_+1][lm_] = v_.y;                             \
    As[lk_+2][lm_] = v_.z; As[lk_+3][lm_] = v_.w; } while (0)

// B tile (BK x BN) from "transposed" source layout [N x ldb] (row = n, col = k)
#define LOAD_B_T(Bsrc, ldb) do {                                              \
    int ln_ = tid >> 2; int lk_ = (tid & 3) << 2;                             \
    const float4 v_ = *(const float4*)((Bsrc) + (size_t)ln_ * (ldb) + lk_);   \
    Bs[lk_+0][ln_] = v_.x; Bs[lk_+1][ln_] = v_.y;                             \
    Bs[lk_+2][ln_] = v_.z; Bs[lk_+3][ln_] = v_.w; } while (0)

// B tile (BK x BN) from natural row-major [K x ldb] (row = k, col = n)
#define LOAD_B_N(Bsrc, ldb) do {                                              \
    int lk_ = tid >> 4; int ln_ = (tid & 15) << 2;                            \
    *(float4*)&Bs[lk_][ln_] =                                                 \
        *(const float4*)((Bsrc) + (size_t)lk_ * (ldb) + ln_); } while (0)

#define MMA_STEP do {                                                         \
    _Pragma("unroll")                                                         \
    for (int kk = 0; kk < BK; ++kk) {                                         \
        float4 a_ = *(const float4*)&As[kk][ty4];                             \
        float4 b_ = *(const float4*)&Bs[kk][tx4];                             \
        acc[0][0]+=a_.x*b_.x; acc[0][1]+=a_.x*b_.y;                           \
        acc[0][2]+=a_.x*b_.z; acc[0][3]+=a_.x*b_.w;                           \
        acc[1][0]+=a_.y*b_.x; acc[1][1]+=a_.y*b_.y;                           \
        acc[1][2]+=a_.y*b_.z; acc[1][3]+=a_.y*b_.w;                           \
        acc[2][0]+=a_.z*b_.x; acc[2][1]+=a_.z*b_.y;                           \
        acc[2][2]+=a_.z*b_.z; acc[2][3]+=a_.z*b_.w;                           \
        acc[3][0]+=a_.w*b_.x; acc[3][1]+=a_.w*b_.y;                           \
        acc[3][2]+=a_.w*b_.z; acc[3][3]+=a_.w*b_.w;                           \
    } } while (0)

// ---- kernels ---------------------------------------------------------------

// Pow[0] = I, Pow[1] = A
__global__ void k_pow_init(const float* __restrict__ A) {
    int idx = blockIdx.x * 256 + threadIdx.x;      // 0..65535
    int r = idx >> 8, c = idx & 255;
    g_Pow[idx] = (r == c) ? 1.f : 0.f;
    g_Pow[65536 + idx] = A[idx];
}

// Pow[lo+i] = Pow[lo] @ Pow[i], i = 1..lo  (doubling level)
__global__ void k_powmul(int lo) {
    int i = blockIdx.z + 1;
    const float* Ap = g_Pow + (size_t)lo * 65536;
    const float* Bp = g_Pow + (size_t)i  * 65536;
    float*       Cp = g_Pow + (size_t)(lo + i) * 65536;
    __shared__ float As[BK][BM], Bs[BK][BN];
    int tid = threadIdx.x;
    int ty4 = (tid >> 4) << 2, tx4 = (tid & 15) << 2;
    int m0 = blockIdx.y * BM, n0 = blockIdx.x * BN;
    float acc[4][4] = {};
    for (int kb = 0; kb < 256; kb += BK) {
        LOAD_A_ROW(Ap + (size_t)m0 * 256 + kb, 256);
        LOAD_B_N(Bp + (size_t)kb * 256 + n0, 256);
        __syncthreads(); MMA_STEP; __syncthreads();
    }
    for (int i2 = 0; i2 < 4; i2++) {
        float4 v = {acc[i2][0], acc[i2][1], acc[i2][2], acc[i2][3]};
        *(float4*)(Cp + (size_t)(m0 + ty4 + i2) * 256 + n0 + tx4) = v;
    }
}

// U = scatter(x @ B^T)  (M=16384, N=256, K=1024)
__global__ void k_gemm1(const float* __restrict__ x, const float* __restrict__ Bm) {
    __shared__ float As[BK][BM], Bs[BK][BN];
    int tid = threadIdx.x;
    int ty4 = (tid >> 4) << 2, tx4 = (tid & 15) << 2;
    int m0 = blockIdx.y * BM, n0 = blockIdx.x * BN;
    float acc[4][4] = {};
    for (int kb = 0; kb < DMODEL; kb += BK) {
        LOAD_A_ROW(x + (size_t)m0 * DMODEL + kb, DMODEL);
        LOAD_B_T(Bm + (size_t)n0 * DMODEL + kb, DMODEL);
        __syncthreads(); MMA_STEP; __syncthreads();
    }
    for (int i = 0; i < 4; i++) {
        int m = m0 + ty4 + i;
        int t = m & (SEQ - 1), b = m >> 11;
        int col  = (t >> 4) * BATCH + b;
        int krow = (t & 15) * NSTATE;
        for (int j = 0; j < 4; j++) {
            int n = n0 + tx4 + j;
            g_U[(size_t)(krow + n) * NCOLS + col] = acc[i][j];
        }
    }
}

// S3 = Tri @ U, Tri block (k,j) = A^(k-j) (skip j>k)  (M=4096, N=1024, K<=4096)
__global__ void k_tri() {
    __shared__ float As[BK][BM], Bs[BK][BN];
    int tid = threadIdx.x;
    int ty4 = (tid >> 4) << 2, tx4 = (tid & 15) << 2;
    int m0 = blockIdx.y * BM, n0 = blockIdx.x * BN;
    int kch = m0 >> 8;
    int Kmax = (kch + 1) * NSTATE;
    float acc[4][4] = {};
    for (int kb = 0; kb < Kmax; kb += BK) {
        int p = kch - (kb >> 8);
        const float* Ap = g_Pow + (size_t)p * 65536 + (size_t)(m0 & 255) * 256 + (kb & 255);
        LOAD_A_ROW(Ap, 256);
        LOAD_B_N(g_U + (size_t)kb * NCOLS + n0, NCOLS);
        __syncthreads(); MMA_STEP; __syncthreads();
    }
    for (int i = 0; i < 4; i++) {
        float4 v = {acc[i][0], acc[i][1], acc[i][2], acc[i][3]};
        *(float4*)(g_S3 + (size_t)(m0 + ty4 + i) * NCOLS + n0 + tx4) = v;
    }
}

// Hc[(k,n)][(i,b)] = A^(k+1) @ boundary(i),  boundary(0)=h0, else S3 row k=15 of chunk i-1
__global__ void k_corr(const float* __restrict__ h0) {
    __shared__ float As[BK][BM], Bs[BK][BN];
    int tid = threadIdx.x;
    int ty4 = (tid >> 4) << 2, tx4 = (tid & 15) << 2;
    int m0 = blockIdx.y * BM, n0 = blockIdx.x * BN;
    int p = (m0 >> 8) + 1;
    const float* Srow = g_S3 + (size_t)(15 * NSTATE) * NCOLS;
    float acc[4][4] = {};
    for (int kb = 0; kb < NSTATE; kb += BK) {
        const float* Ap = g_Pow + (size_t)p * 65536 + (size_t)(m0 & 255) * 256 + kb;
        LOAD_A_ROW(Ap, 256);
        {
            int lk = tid >> 4, ln = (tid & 15) << 2;
            for (int q = 0; q < 4; q++) {
                int col = n0 + ln + q;
                int mm = kb + lk;
                Bs[lk][ln + q] = (col < BATCH) ? h0[mm]
                                               : Srow[(size_t)mm * NCOLS + col - BATCH];
            }
        }
        __syncthreads(); MMA_STEP; __syncthreads();
    }
    for (int i = 0; i < 4; i++) {
        float4 v = {acc[i][0], acc[i][1], acc[i][2], acc[i][3]};
        *(float4*)(g_Hc + (size_t)(m0 + ty4 + i) * NCOLS + n0 + tx4) = v;
    }
}

// hs = S3 + Hc, transposed into [(b,t)][n]; also emit h_final
__global__ void k_combine(float* __restrict__ hf) {
    __shared__ float tile[32][33];
    int tid = threadIdx.x;
    int tx = tid & 31, ty = tid >> 5;
    int c0 = blockIdx.x * 32, r0 = blockIdx.y * 32;
    for (int it = 0; it < 4; it++) {
        int rr = ty + it * 8;
        size_t idx = (size_t)(r0 + rr) * NCOLS + c0 + tx;
        tile[rr][tx] = g_S3[idx] + g_Hc[idx];
    }
    __syncthreads();
    int k = r0 >> 8;
    int n = (r0 & 255) + tx;
    for (int it = 0; it < 4; it++) {
        int cc = ty + it * 8;
        int c = c0 + cc;
        int ich = c >> 3, b = c & 7;
        int t = ich * LCH + k;
        float v = tile[tx][cc];
        g_Hs[((size_t)(b * SEQ + t)) * NSTATE + n] = v;
        if (t == SEQ - 1 && hf) hf[b * NSTATE + n] = v;
    }
}

// y = Hs @ C^T + x @ D^T  (M=16384, N=1024, K=256 then K=1024)
__global__ void k_y(const float* __restrict__ x, const float* __restrict__ Cm,
                    const float* __restrict__ Dm, float* __restrict__ y) {
    __shared__ float As[BK][BM], Bs[BK][BN];
    int tid = threadIdx.x;
    int ty4 = (tid >> 4) << 2, tx4 = (tid & 15) << 2;
    int m0 = blockIdx.y * BM, n0 = blockIdx.x * BN;
    float acc[4][4] = {};
    for (int kb = 0; kb < NSTATE; kb += BK) {
        LOAD_A_ROW(g_Hs + (size_t)m0 * NSTATE + kb, NSTATE);
        LOAD_B_T(Cm + (size_t)n0 * NSTATE + kb, NSTATE);
        __syncthreads(); MMA_STEP; __syncthreads();
    }
    for (int kb = 0; kb < DMODEL; kb += BK) {
        LOAD_A_ROW(x + (size_t)m0 * DMODEL + kb, DMODEL);
        LOAD_B_T(Dm + (size_t)n0 * DMODEL + kb, DMODEL);
        __syncthreads(); MMA_STEP; __syncthreads();
    }
    for (int i = 0; i < 4; i++) {
        float4 v = {acc[i][0], acc[i][1], acc[i][2], acc[i][3]};
        *(float4*)(y + (size_t)(m0 + ty4 + i) * DMODEL + n0 + tx4) = v;
    }
}

// ---- launch ----------------------------------------------------------------
extern "C" void kernel_launch(void* const* d_in, const int* in_sizes, int n_in,
                              void* d_out, int out_size) {
    const float* x  = (const float*)d_in[0];
    const float* A  = (const float*)d_in[1];
    const float* Bm = (const float*)d_in[2];
    const float* Cm = (const float*)d_in[3];
    const float* Dm = (const float*)d_in[4];
    const float* h0 = (const float*)d_in[5];
    float* y  = (float*)d_out;
    float* hf = ((size_t)out_size >= Y_ELEMS + (size_t)BATCH * NSTATE)
                    ? y + Y_ELEMS : (float*)0;

    k_pow_init<<<256, 256>>>(A);
    k_gemm1<<<dim3(NSTATE / BN, MROWS / BM), 256>>>(x, Bm);
    k_powmul<<<dim3(4, 4, 1), 256>>>(1);   // A^2
    k_powmul<<<dim3(4, 4, 2), 256>>>(2);   // A^3..A^4
    k_powmul<<<dim3(4, 4, 4), 256>>>(4);   // A^5..A^8
    k_powmul<<<dim3(4, 4, 8), 256>>>(8);   // A^9..A^16
    k_tri<<<dim3(NCOLS / BN, TRIM / BM), 256>>>();
    k_corr<<<dim3(NCOLS / BN, TRIM / BM), 256>>>(h0);
    k_combine<<<dim3(NCOLS / 32, TRIM / 32), 256>>>(hf);
    k_y<<<dim3(DMODEL / BN, MROWS / BM), 256>>>(x, Cm, Dm, y);
}

// round 5
// speedup vs baseline: 1.4166x; 1.4166x over previous
#include <cuda_runtime.h>
#include <cuda_bf16.h>
#include <cstdint>

#define BATCH  8
#define SEQ    2048
#define DMODEL 1024
#define NSTATE 256
#define LCH    16
#define NCHUNK (SEQ / LCH)            // 128
#define MROWS  (BATCH * SEQ)          // 16384
#define TRIM   (LCH * NSTATE)         // 4096
#define NCOLS  (NCHUNK * BATCH)       // 1024
#define Y_ELEMS ((size_t)MROWS * DMODEL)

// ---------------- static scratch (16B aligned for vector/cp.async access) ----
__device__ __align__(16) float g_Pow[17 * 65536];
__device__ __align__(16) __nv_bfloat16 g_PowHi[17 * 65536], g_PowLo[17 * 65536];
__device__ __align__(16) __nv_bfloat16 g_xHi[(size_t)MROWS * DMODEL], g_xLo[(size_t)MROWS * DMODEL];
__device__ __align__(16) __nv_bfloat16 g_BHi[NSTATE * DMODEL],  g_BLo[NSTATE * DMODEL];
__device__ __align__(16) __nv_bfloat16 g_CHi[DMODEL * NSTATE],  g_CLo[DMODEL * NSTATE];
__device__ __align__(16) __nv_bfloat16 g_DHi[DMODEL * DMODEL],  g_DLo[DMODEL * DMODEL];
__device__ __align__(16) __nv_bfloat16 g_UtHi[(size_t)NCOLS * TRIM], g_UtLo[(size_t)NCOLS * TRIM];
__device__ __align__(16) float g_S3[(size_t)TRIM * NCOLS];
__device__ __align__(16) __nv_bfloat16 g_bndHi[NCOLS * NSTATE], g_bndLo[NCOLS * NSTATE];
__device__ __align__(16) __nv_bfloat16 g_HsHi[(size_t)MROWS * NSTATE], g_HsLo[(size_t)MROWS * NSTATE];

// ---------------- PTX primitives (all arch-agnostic, sm_80+) ----------------
__device__ __forceinline__ uint32_t smem_u32(const void* p) {
    uint32_t a;
    asm("{ .reg .u64 t; cvta.to.shared.u64 t, %1; cvt.u32.u64 %0, t; }" : "=r"(a) : "l"(p));
    return a;
}
#define CPASYNC(s, g) asm volatile("cp.async.cg.shared.global [%0], [%1], 16;" :: "r"(s), "l"(g))
#define CPCOMMIT()    asm volatile("cp.async.commit_group;")
#define CPWAIT1()     asm volatile("cp.async.wait_group 1;")
#define CPWAIT0()     asm volatile("cp.async.wait_group 0;")
#define LDSM4(r, addr) \
    asm volatile("ldmatrix.sync.aligned.m8n8.x4.shared.b16 {%0,%1,%2,%3}, [%4];" \
        : "=r"((r)[0]), "=r"((r)[1]), "=r"((r)[2]), "=r"((r)[3]) : "r"(addr))
#define MMA(d, a, b0, b1) \
    asm volatile("mma.sync.aligned.m16n8k16.row.col.f32.bf16.bf16.f32 " \
        "{%0,%1,%2,%3}, {%4,%5,%6,%7}, {%8,%9}, {%0,%1,%2,%3};" \
        : "+f"((d)[0]), "+f"((d)[1]), "+f"((d)[2]), "+f"((d)[3]) \
        : "r"((a)[0]), "r"((a)[1]), "r"((a)[2]), "r"((a)[3]), "r"(b0), "r"(b1))

// ---------------- HMMA GEMM core: C[128,128] += (Ahi+Alo)(Bhi+Blo)^T --------
// SMEM: 3 stages x 4 tiles (Ahi,Alo,Bhi,Blo), each 128 rows x 64B, pitch 80B.
#define PITCH     80
#define TILE_B    (128 * PITCH)       // 10240
#define STAGE_B   (4 * TILE_B)        // 40960
#define SMEMSZ    (3 * STAGE_B)       // 122880

struct TS { const __nv_bfloat16 *ah, *al, *bh, *bl; int lda, ldb; };

__device__ __forceinline__ void load_stage(uint32_t sb, int stg, const TS& t) {
    int tid = threadIdx.x;
    int tile = tid >> 6;           // 0..3
    int j = tid & 63;
    int chunk = j & 3;             // 16B chunk within 64B row
    const __nv_bfloat16* src = (tile == 0) ? t.ah : (tile == 1) ? t.al
                             : (tile == 2) ? t.bh : t.bl;
    int ld = (tile < 2) ? t.lda : t.ldb;
    uint32_t dbase = sb + stg * STAGE_B + tile * TILE_B + chunk * 16;
    const char* gbase = (const char*)src + chunk * 16;
#pragma unroll
    for (int r8 = 0; r8 < 8; r8++) {
        int row = r8 * 16 + (j >> 2);
        CPASYNC(dbase + row * PITCH, gbase + (size_t)row * ld * 2);
    }
}

template <class P>
__global__ void __launch_bounds__(256, 1) kHG(float* aux) {
    extern __shared__ char smem[];
    int m0 = blockIdx.y * 128, n0 = blockIdx.x * 128;
    uint32_t sb = smem_u32(smem);
    int tid = threadIdx.x, lane = tid & 31, wid = tid >> 5;
    int wm = wid & 1, wn = wid >> 1;
    int nchunks = P::nchunks(m0);

    float acc[4][4][4] = {};
    TS t;
    P::tiles(0, m0, n0, t); load_stage(sb, 0, t); CPCOMMIT();
    P::tiles(1, m0, n0, t); load_stage(sb, 1, t); CPCOMMIT();

    for (int ch = 0; ch < nchunks; ch++) {
        CPWAIT1();
        __syncthreads();
        if (ch + 2 < nchunks) {
            P::tiles(ch + 2, m0, n0, t);
            load_stage(sb, (ch + 2) % 3, t);
            CPCOMMIT();
        }
        uint32_t stg = sb + (ch % 3) * STAGE_B;
        uint32_t aH = stg + (wm * 64 + (lane & 15)) * PITCH + (lane >> 4) * 16;
        uint32_t bH = stg + 2 * TILE_B + (wn * 32 + (lane & 15)) * PITCH + (lane >> 4) * 16;
#pragma unroll
        for (int ks = 0; ks < 2; ks++) {
            int ko = ks * 32;
            uint32_t ah[4][4], al[4][4], bh[2][4], bl[2][4];
#pragma unroll
            for (int mi = 0; mi < 4; mi++) {
                LDSM4(ah[mi], aH + mi * (16 * PITCH) + ko);
                LDSM4(al[mi], aH + mi * (16 * PITCH) + ko + TILE_B);
            }
#pragma unroll
            for (int nb = 0; nb < 2; nb++) {
                LDSM4(bh[nb], bH + nb * (16 * PITCH) + ko);
                LDSM4(bl[nb], bH + nb * (16 * PITCH) + ko + TILE_B);
            }
#pragma unroll
            for (int mi = 0; mi < 4; mi++)
#pragma unroll
                for (int nb = 0; nb < 2; nb++)
#pragma unroll
                    for (int tl = 0; tl < 2; tl++) {
                        float* d = acc[mi][nb * 2 + tl];
                        MMA(d, ah[mi], bh[nb][tl], bh[nb][tl + 2]);
                        MMA(d, ah[mi], bl[nb][tl], bl[nb][tl + 2]);
                        MMA(d, al[mi], bh[nb][tl], bh[nb][tl + 2]);
                    }
        }
    }
    CPWAIT0();
    __syncthreads();

    float* stf = (float*)smem;                 // [128][132]
#pragma unroll
    for (int mi = 0; mi < 4; mi++)
#pragma unroll
        for (int n = 0; n < 4; n++) {
            int r = wm * 64 + mi * 16 + (lane >> 2);
            int c = wn * 32 + n * 8 + (lane & 3) * 2;
            stf[r * 132 + c]           = acc[mi][n][0];
            stf[r * 132 + c + 1]       = acc[mi][n][1];
            stf[(r + 8) * 132 + c]     = acc[mi][n][2];
            stf[(r + 8) * 132 + c + 1] = acc[mi][n][3];
        }
    __syncthreads();
    P::epi(stf, m0, n0, aux);
}

// ---------------- policies ----------------
__device__ __forceinline__ void store_tile_f32(const float* stf, float* dst, int ldd) {
    int tid = threadIdx.x;
#pragma unroll
    for (int it = 0; it < 16; it++) {
        int lin = it * 256 + tid;
        int row = lin >> 5, c4 = (lin & 31) * 4;
        const float* sp = stf + row * 132 + c4;
        float4 v = {sp[0], sp[1], sp[2], sp[3]};
        *(float4*)(dst + (size_t)row * ldd + c4) = v;
    }
}

struct PG1 {   // U = scatter(x @ B^T): M=16384, N=256, K=1024
    static __device__ __forceinline__ int nchunks(int) { return DMODEL / 32; }
    static __device__ __forceinline__ void tiles(int ch, int m0, int n0, TS& t) {
        size_t ao = (size_t)m0 * DMODEL + ch * 32;
        size_t bo = (size_t)n0 * DMODEL + ch * 32;
        t.ah = g_xHi + ao; t.al = g_xLo + ao; t.lda = DMODEL;
        t.bh = g_BHi + bo; t.bl = g_BLo + bo; t.ldb = DMODEL;
    }
    static __device__ __forceinline__ void epi(float* stf, int m0, int n0, float*) {
        int tid = threadIdx.x;
#pragma unroll
        for (int it = 0; it < 16; it++) {
            int lin = it * 256 + tid;
            int row = lin >> 5, c4 = (lin & 31) * 4;
            int m = m0 + row, b = m >> 11, tt = m & 2047;
            size_t base = (size_t)((tt >> 4) * 8 + b) * 4096 + (tt & 15) * 256 + n0 + c4;
            const float* sp = stf + row * 132 + c4;
            float v0 = sp[0], v1 = sp[1], v2 = sp[2], v3 = sp[3];
            __nv_bfloat16 h0 = __float2bfloat16(v0), h1 = __float2bfloat16(v1);
            __nv_bfloat16 h2 = __float2bfloat16(v2), h3 = __float2bfloat16(v3);
            *(__nv_bfloat162*)&g_UtHi[base]     = __halves2bfloat162(h0, h1);
            *(__nv_bfloat162*)&g_UtHi[base + 2] = __halves2bfloat162(h2, h3);
            __nv_bfloat16 l0 = __float2bfloat16(v0 - __bfloat162float(h0));
            __nv_bfloat16 l1 = __float2bfloat16(v1 - __bfloat162float(h1));
            __nv_bfloat16 l2 = __float2bfloat16(v2 - __bfloat162float(h2));
            __nv_bfloat16 l3 = __float2bfloat16(v3 - __bfloat162float(h3));
            *(__nv_bfloat162*)&g_UtLo[base]     = __halves2bfloat162(l0, l1);
            *(__nv_bfloat162*)&g_UtLo[base + 2] = __halves2bfloat162(l2, l3);
        }
    }
};

struct PTRI {  // S3 = Tri @ U: M=4096, N=1024, K=(kch+1)*256
    static __device__ __forceinline__ int nchunks(int m0) { return ((m0 >> 8) + 1) * 8; }
    static __device__ __forceinline__ void tiles(int ch, int m0, int n0, TS& t) {
        int p = (m0 >> 8) - (ch >> 3);
        size_t ao = (size_t)p * 65536 + (size_t)(m0 & 255) * 256 + (ch & 7) * 32;
        size_t bo = (size_t)n0 * 4096 + ch * 32;
        t.ah = g_PowHi + ao; t.al = g_PowLo + ao; t.lda = 256;
        t.bh = g_UtHi + bo;  t.bl = g_UtLo + bo;  t.ldb = 4096;
    }
    static __device__ __forceinline__ void epi(float* stf, int m0, int n0, float*) {
        store_tile_f32(stf, g_S3 + (size_t)m0 * 1024 + n0, 1024);
    }
};

struct PCORR { // Hc = A^(k+1) @ bnd; out = S3 + Hc -> Hs(split) + h_final
    static __device__ __forceinline__ int nchunks(int) { return NSTATE / 32; }
    static __device__ __forceinline__ void tiles(int ch, int m0, int n0, TS& t) {
        int p = (m0 >> 8) + 1;
        size_t ao = (size_t)p * 65536 + (size_t)(m0 & 255) * 256 + ch * 32;
        size_t bo = (size_t)n0 * 256 + ch * 32;
        t.ah = g_PowHi + ao;  t.al = g_PowLo + ao;  t.lda = 256;
        t.bh = g_bndHi + bo;  t.bl = g_bndLo + bo;  t.ldb = 256;
    }
    static __device__ __forceinline__ void epi(float* stf, int m0, int n0, float* hf) {
        int tid = threadIdx.x;
#pragma unroll
        for (int it = 0; it < 16; it++) {
            int lin = it * 256 + tid;
            int row = lin >> 5, c4 = (lin & 31) * 4;
            float4 sv = *(const float4*)(g_S3 + (size_t)(m0 + row) * 1024 + n0 + c4);
            float* sp = stf + row * 132 + c4;
            sp[0] += sv.x; sp[1] += sv.y; sp[2] += sv.z; sp[3] += sv.w;
        }
        __syncthreads();
        int k = m0 >> 8, s0 = m0 & 255;
        int c = tid >> 1, half = tid & 1;
        int n = n0 + c, ic = n >> 3, b = n & 7;
        size_t hsbase = (size_t)(b * SEQ + ic * LCH + k) * 256 + s0;
        bool fin = (k == 15) && (ic == 127) && (hf != nullptr);
#pragma unroll
        for (int i = 0; i < 64; i++) {
            int row = half * 64 + i;
            float v = stf[row * 132 + c];
            __nv_bfloat16 h = __float2bfloat16(v);
            g_HsHi[hsbase + row] = h;
            g_HsLo[hsbase + row] = __float2bfloat16(v - __bfloat162float(h));
            if (fin) hf[b * 256 + s0 + row] = v;
        }
    }
};

struct PY {    // y = Hs @ C^T + x @ D^T: M=16384, N=1024, K=256+1024
    static __device__ __forceinline__ int nchunks(int) { return 8 + 32; }
    static __device__ __forceinline__ void tiles(int ch, int m0, int n0, TS& t) {
        if (ch < 8) {
            size_t ao = (size_t)m0 * 256 + ch * 32;
            size_t bo = (size_t)n0 * 256 + ch * 32;
            t.ah = g_HsHi + ao; t.al = g_HsLo + ao; t.lda = 256;
            t.bh = g_CHi + bo;  t.bl = g_CLo + bo;  t.ldb = 256;
        } else {
            int cc = ch - 8;
            size_t ao = (size_t)m0 * DMODEL + cc * 32;
            size_t bo = (size_t)n0 * DMODEL + cc * 32;
            t.ah = g_xHi + ao; t.al = g_xLo + ao; t.lda = DMODEL;
            t.bh = g_DHi + bo; t.bl = g_DLo + bo; t.ldb = DMODEL;
        }
    }
    static __device__ __forceinline__ void epi(float* stf, int m0, int n0, float* y) {
        store_tile_f32(stf, y + (size_t)m0 * 1024 + n0, 1024);
    }
};

// ---------------- f32 SIMT powers ----------------
#define BM 64
#define BN 64
#define BK 16
#define LOAD_A_ROW(Asrc, lda) do {                                            \
    int lm_ = tid >> 2; int lk_ = (tid & 3) << 2;                             \
    const float4 v_ = *(const float4*)((Asrc) + (size_t)lm_ * (lda) + lk_);   \
    As[lk_+0][lm_] = v_.x; As[lk_+1][lm_] = v_.y;                             \
    As[lk_+2][lm_] = v_.z; As[lk_+3][lm_] = v_.w; } while (0)
#define LOAD_B_N(Bsrc, ldb) do {                                              \
    int lk_ = tid >> 4; int ln_ = (tid & 15) << 2;                            \
    *(float4*)&Bs[lk_][ln_] =                                                 \
        *(const float4*)((Bsrc) + (size_t)lk_ * (ldb) + ln_); } while (0)
#define MMA_STEP do {                                                         \
    _Pragma("unroll")                                                         \
    for (int kk = 0; kk < BK; ++kk) {                                         \
        float4 a_ = *(const float4*)&As[kk][ty4];                             \
        float4 b_ = *(const float4*)&Bs[kk][tx4];                             \
        acc[0][0]+=a_.x*b_.x; acc[0][1]+=a_.x*b_.y;                           \
        acc[0][2]+=a_.x*b_.z; acc[0][3]+=a_.x*b_.w;                           \
        acc[1][0]+=a_.y*b_.x; acc[1][1]+=a_.y*b_.y;                           \
        acc[1][2]+=a_.y*b_.z; acc[1][3]+=a_.y*b_.w;                           \
        acc[2][0]+=a_.z*b_.x; acc[2][1]+=a_.z*b_.y;                           \
        acc[2][2]+=a_.z*b_.z; acc[2][3]+=a_.z*b_.w;                           \
        acc[3][0]+=a_.w*b_.x; acc[3][1]+=a_.w*b_.y;                           \
        acc[3][2]+=a_.w*b_.z; acc[3][3]+=a_.w*b_.w;                           \
    } } while (0)

__global__ void k_pow_init(const float* __restrict__ A) {
    int idx = blockIdx.x * 256 + threadIdx.x;
    int r = idx >> 8, c = idx & 255;
    g_Pow[idx] = (r == c) ? 1.f : 0.f;
    g_Pow[65536 + idx] = A[idx];
}

__global__ void k_powmul(int lo) {
    int i = blockIdx.z + 1;
    const float* Ap = g_Pow + (size_t)lo * 65536;
    const float* Bp = g_Pow + (size_t)i  * 65536;
    float*       Cp = g_Pow + (size_t)(lo + i) * 65536;
    __shared__ float As[BK][BM], Bs[BK][BN];
    int tid = threadIdx.x;
    int ty4 = (tid >> 4) << 2, tx4 = (tid & 15) << 2;
    int m0 = blockIdx.y * BM, n0 = blockIdx.x * BN;
    float acc[4][4] = {};
    for (int kb = 0; kb < 256; kb += BK) {
        LOAD_A_ROW(Ap + (size_t)m0 * 256 + kb, 256);
        LOAD_B_N(Bp + (size_t)kb * 256 + n0, 256);
        __syncthreads(); MMA_STEP; __syncthreads();
    }
    for (int i2 = 0; i2 < 4; i2++) {
        float4 v = {acc[i2][0], acc[i2][1], acc[i2][2], acc[i2][3]};
        *(float4*)(Cp + (size_t)(m0 + ty4 + i2) * 256 + n0 + tx4) = v;
    }
}

// ---------------- split / misc kernels ----------------
__device__ __forceinline__ void split4(const float4 v, __nv_bfloat16* hi, __nv_bfloat16* lo, size_t i4) {
    __nv_bfloat16 h0 = __float2bfloat16(v.x), h1 = __float2bfloat16(v.y);
    __nv_bfloat16 h2 = __float2bfloat16(v.z), h3 = __float2bfloat16(v.w);
    ((__nv_bfloat162*)hi)[i4 * 2 + 0] = __halves2bfloat162(h0, h1);
    ((__nv_bfloat162*)hi)[i4 * 2 + 1] = __halves2bfloat162(h2, h3);
    __nv_bfloat16 l0 = __float2bfloat16(v.x - __bfloat162float(h0));
    __nv_bfloat16 l1 = __float2bfloat16(v.y - __bfloat162float(h1));
    __nv_bfloat16 l2 = __float2bfloat16(v.z - __bfloat162float(h2));
    __nv_bfloat16 l3 = __float2bfloat16(v.w - __bfloat162float(h3));
    ((__nv_bfloat162*)lo)[i4 * 2 + 0] = __halves2bfloat162(l0, l1);
    ((__nv_bfloat162*)lo)[i4 * 2 + 1] = __halves2bfloat162(l2, l3);
}
__global__ void k_split_x(const float* __restrict__ s) {
    size_t i = (size_t)blockIdx.x * 256 + threadIdx.x;
    if (i < (size_t)MROWS * DMODEL / 4) split4(((const float4*)s)[i], g_xHi, g_xLo, i);
}
__global__ void k_split_B(const float* __restrict__ s) {
    size_t i = (size_t)blockIdx.x * 256 + threadIdx.x;
    if (i < (size_t)NSTATE * DMODEL / 4) split4(((const float4*)s)[i], g_BHi, g_BLo, i);
}
__global__ void k_split_C(const float* __restrict__ s) {
    size_t i = (size_t)blockIdx.x * 256 + threadIdx.x;
    if (i < (size_t)DMODEL * NSTATE / 4) split4(((const float4*)s)[i], g_CHi, g_CLo, i);
}
__global__ void k_split_D(const float* __restrict__ s) {
    size_t i = (size_t)blockIdx.x * 256 + threadIdx.x;
    if (i < (size_t)DMODEL * DMODEL / 4) split4(((const float4*)s)[i], g_DHi, g_DLo, i);
}
__global__ void k_split_pow() {
    size_t i = (size_t)blockIdx.x * 256 + threadIdx.x;
    if (i < (size_t)17 * 65536 / 4) split4(((const float4*)g_Pow)[i], g_PowHi, g_PowLo, i);
}
__global__ void k_bnd(const float* __restrict__ h0) {
    int idx = blockIdx.x * 256 + threadIdx.x;   // 1024*256
    int c = idx >> 8, s = idx & 255;
    float v = (c < 8) ? h0[s] : g_S3[(size_t)(3840 + s) * 1024 + (c - 8)];
    __nv_bfloat16 h = __float2bfloat16(v);
    g_bndHi[idx] = h;
    g_bndLo[idx] = __float2bfloat16(v - __bfloat162float(h));
}

// ---------------- launch ----------------
extern "C" void kernel_launch(void* const* d_in, const int* in_sizes, int n_in,
                              void* d_out, int out_size) {
    const float* x  = (const float*)d_in[0];
    const float* A  = (const float*)d_in[1];
    const float* Bm = (const float*)d_in[2];
    const float* Cm = (const float*)d_in[3];
    const float* Dm = (const float*)d_in[4];
    const float* h0 = (const float*)d_in[5];
    float* y  = (float*)d_out;
    float* hf = ((size_t)out_size >= Y_ELEMS + (size_t)BATCH * NSTATE)
                    ? y + Y_ELEMS : (float*)0;

    cudaFuncSetAttribute(kHG<PG1>,   cudaFuncAttributeMaxDynamicSharedMemorySize, SMEMSZ);
    cudaFuncSetAttribute(kHG<PTRI>,  cudaFuncAttributeMaxDynamicSharedMemorySize, SMEMSZ);
    cudaFuncSetAttribute(kHG<PCORR>, cudaFuncAttributeMaxDynamicSharedMemorySize, SMEMSZ);
    cudaFuncSetAttribute(kHG<PY>,    cudaFuncAttributeMaxDynamicSharedMemorySize, SMEMSZ);

    k_pow_init<<<256, 256>>>(A);
    k_split_x<<<MROWS * DMODEL / 4 / 256, 256>>>(x);
    k_split_B<<<NSTATE * DMODEL / 4 / 256, 256>>>(Bm);
    k_split_C<<<DMODEL * NSTATE / 4 / 256, 256>>>(Cm);
    k_split_D<<<DMODEL * DMODEL / 4 / 256, 256>>>(Dm);
    k_powmul<<<dim3(4, 4, 1), 256>>>(1);
    k_powmul<<<dim3(4, 4, 2), 256>>>(2);
    k_powmul<<<dim3(4, 4, 4), 256>>>(4);
    k_powmul<<<dim3(4, 4, 8), 256>>>(8);
    k_split_pow<<<17 * 65536 / 4 / 256, 256>>>();
    kHG<PG1><<<dim3(NSTATE / 128, MROWS / 128), 256, SMEMSZ>>>(nullptr);
    kHG<PTRI><<<dim3(NCOLS / 128, TRIM / 128), 256, SMEMSZ>>>(nullptr);
    k_bnd<<<NCOLS * NSTATE / 256, 256>>>(h0);
    kHG<PCORR><<<dim3(NCOLS / 128, TRIM / 128), 256, SMEMSZ>>>(hf);
    kHG<PY><<<dim3(DMODEL / 128, MROWS / 128), 256, SMEMSZ>>>(y);
}

// round 6
// speedup vs baseline: 2.3394x; 1.6515x over previous
#include <cuda_runtime.h>
#include <cuda_bf16.h>
#include <cstdint>

#define BATCH  8
#define SEQ    2048
#define DMODEL 1024
#define NSTATE 256
#define LCH    16
#define NCHUNK (SEQ / LCH)            // 128
#define MROWS  (BATCH * SEQ)          // 16384
#define TRIM   (LCH * NSTATE)         // 4096
#define NCOLS  (NCHUNK * BATCH)       // 1024
#define Y_ELEMS ((size_t)MROWS * DMODEL)

// ---------------- static scratch ----------------
__device__ __align__(16) float g_Pow[17 * 65536];
__device__ __align__(16) __nv_bfloat16 g_PowHi[17 * 65536], g_PowLo[17 * 65536];
__device__ __align__(16) __nv_bfloat16 g_xHi[(size_t)MROWS * DMODEL], g_xLo[(size_t)MROWS * DMODEL];
__device__ __align__(16) __nv_bfloat16 g_BHi[NSTATE * DMODEL],  g_BLo[NSTATE * DMODEL];
__device__ __align__(16) __nv_bfloat16 g_CHi[DMODEL * NSTATE],  g_CLo[DMODEL * NSTATE];
__device__ __align__(16) __nv_bfloat16 g_DHi[DMODEL * DMODEL],  g_DLo[DMODEL * DMODEL];
__device__ __align__(16) __nv_bfloat16 g_UtHi[(size_t)NCOLS * TRIM], g_UtLo[(size_t)NCOLS * TRIM];
__device__ __align__(16) float g_S3[(size_t)TRIM * NCOLS];
__device__ __align__(16) __nv_bfloat16 g_bndHi[NCOLS * NSTATE], g_bndLo[NCOLS * NSTATE];
__device__ __align__(16) __nv_bfloat16 g_HsHi[(size_t)MROWS * NSTATE], g_HsLo[(size_t)MROWS * NSTATE];

// ---------------- PTX primitives ----------------
__device__ __forceinline__ uint32_t smem_u32(const void* p) {
    uint32_t a;
    asm("{ .reg .u64 t; cvta.to.shared.u64 t, %1; cvt.u32.u64 %0, t; }" : "=r"(a) : "l"(p));
    return a;
}
#define CPASYNC(s, g) asm volatile("cp.async.cg.shared.global [%0], [%1], 16;" :: "r"(s), "l"(g))
#define CPCOMMIT()    asm volatile("cp.async.commit_group;")
#define CPWAIT1()     asm volatile("cp.async.wait_group 1;")
#define CPWAIT0()     asm volatile("cp.async.wait_group 0;")
#define LDSM4(r, addr) \
    asm volatile("ldmatrix.sync.aligned.m8n8.x4.shared.b16 {%0,%1,%2,%3}, [%4];" \
        : "=r"((r)[0]), "=r"((r)[1]), "=r"((r)[2]), "=r"((r)[3]) : "r"(addr))
#define MMA(d, a, b0, b1) \
    asm volatile("mma.sync.aligned.m16n8k16.row.col.f32.bf16.bf16.f32 " \
        "{%0,%1,%2,%3}, {%4,%5,%6,%7}, {%8,%9}, {%0,%1,%2,%3};" \
        : "+f"((d)[0]), "+f"((d)[1]), "+f"((d)[2]), "+f"((d)[3]) \
        : "r"((a)[0]), "r"((a)[1]), "r"((a)[2]), "r"((a)[3]), "r"(b0), "r"(b1))

// SMEM: 3 stages x 4 tiles (Ahi,Alo,Bhi,Blo), each 128 rows x 64B, pitch 80B.
#define PITCH     80
#define TILE_B    (128 * PITCH)       // 10240
#define STAGE_B   (4 * TILE_B)        // 40960
#define SMEMSZ    (3 * STAGE_B)       // 122880
#define NTHREADS  512

struct TS { const __nv_bfloat16 *ah, *al, *bh, *bl; int lda, ldb; };

__device__ __forceinline__ void load_stage(uint32_t sb, int stg, const TS& t) {
    int tid = threadIdx.x;
    int tile = tid >> 7;           // 0..3
    int j = tid & 127;
    int chunk = j & 3;             // 16B chunk within 64B row
    const __nv_bfloat16* src = (tile == 0) ? t.ah : (tile == 1) ? t.al
                             : (tile == 2) ? t.bh : t.bl;
    int ld = (tile < 2) ? t.lda : t.ldb;
    uint32_t dbase = sb + stg * STAGE_B + tile * TILE_B + chunk * 16;
    const char* gbase = (const char*)src + chunk * 16;
#pragma unroll
    for (int r = 0; r < 4; r++) {
        int row = r * 32 + (j >> 2);
        CPASYNC(dbase + row * PITCH, gbase + (size_t)row * ld * 2);
    }
}

// 16 warps: wm = wid>>2 (M block of 32), wn = wid&3 (N block of 32)
template <class P>
__global__ void __launch_bounds__(NTHREADS, 1) kHG(float* aux) {
    extern __shared__ char smem[];
    int m0 = blockIdx.y * 128, n0 = blockIdx.x * 128;
    uint32_t sb = smem_u32(smem);
    int tid = threadIdx.x, lane = tid & 31, wid = tid >> 5;
    int wm = wid >> 2, wn = wid & 3;
    int nchunks = P::nchunks(m0);

    float acc[2][4][4] = {};
    TS t;
    P::tiles(0, m0, n0, t); load_stage(sb, 0, t); CPCOMMIT();
    P::tiles(1, m0, n0, t); load_stage(sb, 1, t); CPCOMMIT();

    for (int ch = 0; ch < nchunks; ch++) {
        CPWAIT1();
        __syncthreads();
        if (ch + 2 < nchunks) {
            P::tiles(ch + 2, m0, n0, t);
            load_stage(sb, (ch + 2) % 3, t);
            CPCOMMIT();
        }
        uint32_t stg = sb + (ch % 3) * STAGE_B;
        uint32_t aH = stg + (wm * 32 + (lane & 15)) * PITCH + (lane >> 4) * 16;
        uint32_t bH = stg + 2 * TILE_B + (wn * 32 + (lane & 15)) * PITCH + (lane >> 4) * 16;
#pragma unroll
        for (int ks = 0; ks < 2; ks++) {
            int ko = ks * 32;
            uint32_t ah[2][4], al[2][4], bh[2][4], bl[2][4];
#pragma unroll
            for (int mi = 0; mi < 2; mi++) {
                LDSM4(ah[mi], aH + mi * (16 * PITCH) + ko);
                LDSM4(al[mi], aH + mi * (16 * PITCH) + ko + TILE_B);
            }
#pragma unroll
            for (int nb = 0; nb < 2; nb++) {
                LDSM4(bh[nb], bH + nb * (16 * PITCH) + ko);
                LDSM4(bl[nb], bH + nb * (16 * PITCH) + ko + TILE_B);
            }
#pragma unroll
            for (int mi = 0; mi < 2; mi++)
#pragma unroll
                for (int nb = 0; nb < 2; nb++)
#pragma unroll
                    for (int tl = 0; tl < 2; tl++) {
                        float* d = acc[mi][nb * 2 + tl];
                        MMA(d, ah[mi], bh[nb][tl], bh[nb][tl + 2]);
                        MMA(d, ah[mi], bl[nb][tl], bl[nb][tl + 2]);
                        MMA(d, al[mi], bh[nb][tl], bh[nb][tl + 2]);
                    }
        }
    }
    CPWAIT0();
    __syncthreads();

    float* stf = (float*)smem;                 // [128][132] = 67584B
#pragma unroll
    for (int mi = 0; mi < 2; mi++)
#pragma unroll
        for (int n = 0; n < 4; n++) {
            int r = wm * 32 + mi * 16 + (lane >> 2);
            int c = wn * 32 + (n >> 1) * 16 + (n & 1) * 8 + (lane & 3) * 2;
            stf[r * 132 + c]           = acc[mi][n][0];
            stf[r * 132 + c + 1]       = acc[mi][n][1];
            stf[(r + 8) * 132 + c]     = acc[mi][n][2];
            stf[(r + 8) * 132 + c + 1] = acc[mi][n][3];
        }
    __syncthreads();
    P::epi(stf, m0, n0, aux);
}

// ---------------- policies ----------------
__device__ __forceinline__ void store_tile_f32(const float* stf, float* dst, int ldd) {
    int tid = threadIdx.x;
#pragma unroll
    for (int it = 0; it < 8; it++) {
        int lin = it * NTHREADS + tid;
        int row = lin >> 5, c4 = (lin & 31) * 4;
        const float* sp = stf + row * 132 + c4;
        float4 v = {sp[0], sp[1], sp[2], sp[3]};
        *(float4*)(dst + (size_t)row * ldd + c4) = v;
    }
}

struct PG1 {   // U = scatter(x @ B^T): M=16384, N=256, K=1024
    static __device__ __forceinline__ int nchunks(int) { return DMODEL / 32; }
    static __device__ __forceinline__ void tiles(int ch, int m0, int n0, TS& t) {
        size_t ao = (size_t)m0 * DMODEL + ch * 32;
        size_t bo = (size_t)n0 * DMODEL + ch * 32;
        t.ah = g_xHi + ao; t.al = g_xLo + ao; t.lda = DMODEL;
        t.bh = g_BHi + bo; t.bl = g_BLo + bo; t.ldb = DMODEL;
    }
    static __device__ __forceinline__ void epi(float* stf, int m0, int n0, float*) {
        int tid = threadIdx.x;
#pragma unroll
        for (int it = 0; it < 8; it++) {
            int lin = it * NTHREADS + tid;
            int row = lin >> 5, c4 = (lin & 31) * 4;
            int m = m0 + row, b = m >> 11, tt = m & 2047;
            size_t base = (size_t)((tt >> 4) * 8 + b) * 4096 + (tt & 15) * 256 + n0 + c4;
            const float* sp = stf + row * 132 + c4;
            float v0 = sp[0], v1 = sp[1], v2 = sp[2], v3 = sp[3];
            __nv_bfloat16 h0 = __float2bfloat16(v0), h1 = __float2bfloat16(v1);
            __nv_bfloat16 h2 = __float2bfloat16(v2), h3 = __float2bfloat16(v3);
            *(__nv_bfloat162*)&g_UtHi[base]     = __halves2bfloat162(h0, h1);
            *(__nv_bfloat162*)&g_UtHi[base + 2] = __halves2bfloat162(h2, h3);
            __nv_bfloat16 l0 = __float2bfloat16(v0 - __bfloat162float(h0));
            __nv_bfloat16 l1 = __float2bfloat16(v1 - __bfloat162float(h1));
            __nv_bfloat16 l2 = __float2bfloat16(v2 - __bfloat162float(h2));
            __nv_bfloat16 l3 = __float2bfloat16(v3 - __bfloat162float(h3));
            *(__nv_bfloat162*)&g_UtLo[base]     = __halves2bfloat162(l0, l1);
            *(__nv_bfloat162*)&g_UtLo[base + 2] = __halves2bfloat162(l2, l3);
        }
    }
};

struct PTRI {  // S3 = Tri @ U: M=4096, N=1024, K=(kch+1)*256
    static __device__ __forceinline__ int nchunks(int m0) { return ((m0 >> 8) + 1) * 8; }
    static __device__ __forceinline__ void tiles(int ch, int m0, int n0, TS& t) {
        int p = (m0 >> 8) - (ch >> 3);
        size_t ao = (size_t)p * 65536 + (size_t)(m0 & 255) * 256 + (ch & 7) * 32;
        size_t bo = (size_t)n0 * 4096 + ch * 32;
        t.ah = g_PowHi + ao; t.al = g_PowLo + ao; t.lda = 256;
        t.bh = g_UtHi + bo;  t.bl = g_UtLo + bo;  t.ldb = 4096;
    }
    static __device__ __forceinline__ void epi(float* stf, int m0, int n0, float*) {
        store_tile_f32(stf, g_S3 + (size_t)m0 * 1024 + n0, 1024);
    }
};

struct PCORR { // Hc = A^(k+1) @ bnd; out = S3 + Hc -> Hs(split) + h_final
    static __device__ __forceinline__ int nchunks(int) { return NSTATE / 32; }
    static __device__ __forceinline__ void tiles(int ch, int m0, int n0, TS& t) {
        int p = (m0 >> 8) + 1;
        size_t ao = (size_t)p * 65536 + (size_t)(m0 & 255) * 256 + ch * 32;
        size_t bo = (size_t)n0 * 256 + ch * 32;
        t.ah = g_PowHi + ao;  t.al = g_PowLo + ao;  t.lda = 256;
        t.bh = g_bndHi + bo;  t.bl = g_bndLo + bo;  t.ldb = 256;
    }
    static __device__ __forceinline__ void epi(float* stf, int m0, int n0, float* hf) {
        int tid = threadIdx.x;
#pragma unroll
        for (int it = 0; it < 8; it++) {
            int lin = it * NTHREADS + tid;
            int row = lin >> 5, c4 = (lin & 31) * 4;
            float4 sv = *(const float4*)(g_S3 + (size_t)(m0 + row) * 1024 + n0 + c4);
            float* sp = stf + row * 132 + c4;
            sp[0] += sv.x; sp[1] += sv.y; sp[2] += sv.z; sp[3] += sv.w;
        }
        __syncthreads();
        int k = m0 >> 8, s0 = m0 & 255;
        int c = tid >> 2, q = tid & 3;
        int n = n0 + c, ic = n >> 3, b = n & 7;
        size_t hsbase = (size_t)(b * SEQ + ic * LCH + k) * 256 + s0;
        bool fin = (k == 15) && (ic == 127) && (hf != nullptr);
#pragma unroll
        for (int i = 0; i < 32; i++) {
            int row = q * 32 + i;
            float v = stf[row * 132 + c];
            __nv_bfloat16 h = __float2bfloat16(v);
            g_HsHi[hsbase + row] = h;
            g_HsLo[hsbase + row] = __float2bfloat16(v - __bfloat162float(h));
            if (fin) hf[b * 256 + s0 + row] = v;
        }
    }
};

struct PY {    // y = Hs @ C^T + x @ D^T: M=16384, N=1024, K=256+1024
    static __device__ __forceinline__ int nchunks(int) { return 8 + 32; }
    static __device__ __forceinline__ void tiles(int ch, int m0, int n0, TS& t) {
        if (ch < 8) {
            size_t ao = (size_t)m0 * 256 + ch * 32;
            size_t bo = (size_t)n0 * 256 + ch * 32;
            t.ah = g_HsHi + ao; t.al = g_HsLo + ao; t.lda = 256;
            t.bh = g_CHi + bo;  t.bl = g_CLo + bo;  t.ldb = 256;
        } else {
            int cc = ch - 8;
            size_t ao = (size_t)m0 * DMODEL + cc * 32;
            size_t bo = (size_t)n0 * DMODEL + cc * 32;
            t.ah = g_xHi + ao; t.al = g_xLo + ao; t.lda = DMODEL;
            t.bh = g_DHi + bo; t.bl = g_DLo + bo; t.ldb = DMODEL;
        }
    }
    static __device__ __forceinline__ void epi(float* stf, int m0, int n0, float* y) {
        store_tile_f32(stf, y + (size_t)m0 * 1024 + n0, 1024);
    }
};

// ---------------- f32 SIMT powers ----------------
#define BM 64
#define BN 64
#define BK 16
#define LOAD_A_ROW(Asrc, lda) do {                                            \
    int lm_ = tid >> 2; int lk_ = (tid & 3) << 2;                             \
    const float4 v_ = *(const float4*)((Asrc) + (size_t)lm_ * (lda) + lk_);   \
    As[lk_+0][lm_] = v_.x; As[lk_+1][lm_] = v_.y;                             \
    As[lk_+2][lm_] = v_.z; As[lk_+3][lm_] = v_.w; } while (0)
#define LOAD_B_N(Bsrc, ldb) do {                                              \
    int lk_ = tid >> 4; int ln_ = (tid & 15) << 2;                            \
    *(float4*)&Bs[lk_][ln_] =                                                 \
        *(const float4*)((Bsrc) + (size_t)lk_ * (ldb) + ln_); } while (0)
#define MMA_STEP do {                                                         \
    _Pragma("unroll")                                                         \
    for (int kk = 0; kk < BK; ++kk) {                                         \
        float4 a_ = *(const float4*)&As[kk][ty4];                             \
        float4 b_ = *(const float4*)&Bs[kk][tx4];                             \
        acc[0][0]+=a_.x*b_.x; acc[0][1]+=a_.x*b_.y;                           \
        acc[0][2]+=a_.x*b_.z; acc[0][3]+=a_.x*b_.w;                           \
        acc[1][0]+=a_.y*b_.x; acc[1][1]+=a_.y*b_.y;                           \
        acc[1][2]+=a_.y*b_.z; acc[1][3]+=a_.y*b_.w;                           \
        acc[2][0]+=a_.z*b_.x; acc[2][1]+=a_.z*b_.y;                           \
        acc[2][2]+=a_.z*b_.z; acc[2][3]+=a_.z*b_.w;                           \
        acc[3][0]+=a_.w*b_.x; acc[3][1]+=a_.w*b_.y;                           \
        acc[3][2]+=a_.w*b_.z; acc[3][3]+=a_.w*b_.w;                           \
    } } while (0)

__global__ void k_pow_init(const float* __restrict__ A) {
    int idx = blockIdx.x * 256 + threadIdx.x;
    int r = idx >> 8, c = idx & 255;
    g_Pow[idx] = (r == c) ? 1.f : 0.f;
    g_Pow[65536 + idx] = A[idx];
}

__global__ void k_powmul(int lo) {
    int i = blockIdx.z + 1;
    const float* Ap = g_Pow + (size_t)lo * 65536;
    const float* Bp = g_Pow + (size_t)i  * 65536;
    float*       Cp = g_Pow + (size_t)(lo + i) * 65536;
    __shared__ float As[BK][BM], Bs[BK][BN];
    int tid = threadIdx.x;
    int ty4 = (tid >> 4) << 2, tx4 = (tid & 15) << 2;
    int m0 = blockIdx.y * BM, n0 = blockIdx.x * BN;
    float acc[4][4] = {};
    for (int kb = 0; kb < 256; kb += BK) {
        LOAD_A_ROW(Ap + (size_t)m0 * 256 + kb, 256);
        LOAD_B_N(Bp + (size_t)kb * 256 + n0, 256);
        __syncthreads(); MMA_STEP; __syncthreads();
    }
    for (int i2 = 0; i2 < 4; i2++) {
        float4 v = {acc[i2][0], acc[i2][1], acc[i2][2], acc[i2][3]};
        *(float4*)(Cp + (size_t)(m0 + ty4 + i2) * 256 + n0 + tx4) = v;
    }
}

// ---------------- split / misc kernels ----------------
__device__ __forceinline__ void split4(const float4 v, __nv_bfloat16* hi, __nv_bfloat16* lo, size_t i4) {
    __nv_bfloat16 h0 = __float2bfloat16(v.x), h1 = __float2bfloat16(v.y);
    __nv_bfloat16 h2 = __float2bfloat16(v.z), h3 = __float2bfloat16(v.w);
    ((__nv_bfloat162*)hi)[i4 * 2 + 0] = __halves2bfloat162(h0, h1);
    ((__nv_bfloat162*)hi)[i4 * 2 + 1] = __halves2bfloat162(h2, h3);
    __nv_bfloat16 l0 = __float2bfloat16(v.x - __bfloat162float(h0));
    __nv_bfloat16 l1 = __float2bfloat16(v.y - __bfloat162float(h1));
    __nv_bfloat16 l2 = __float2bfloat16(v.z - __bfloat162float(h2));
    __nv_bfloat16 l3 = __float2bfloat16(v.w - __bfloat162float(h3));
    ((__nv_bfloat162*)lo)[i4 * 2 + 0] = __halves2bfloat162(l0, l1);
    ((__nv_bfloat162*)lo)[i4 * 2 + 1] = __halves2bfloat162(l2, l3);
}
__global__ void k_split_x(const float* __restrict__ s) {
    size_t i = (size_t)blockIdx.x * 256 + threadIdx.x;
    if (i < (size_t)MROWS * DMODEL / 4) split4(((const float4*)s)[i], g_xHi, g_xLo, i);
}
__global__ void k_split_B(const float* __restrict__ s) {
    size_t i = (size_t)blockIdx.x * 256 + threadIdx.x;
    if (i < (size_t)NSTATE * DMODEL / 4) split4(((const float4*)s)[i], g_BHi, g_BLo, i);
}
__global__ void k_split_C(const float* __restrict__ s) {
    size_t i = (size_t)blockIdx.x * 256 + threadIdx.x;
    if (i < (size_t)DMODEL * NSTATE / 4) split4(((const float4*)s)[i], g_CHi, g_CLo, i);
}
__global__ void k_split_D(const float* __restrict__ s) {
    size_t i = (size_t)blockIdx.x * 256 + threadIdx.x;
    if (i < (size_t)DMODEL * DMODEL / 4) split4(((const float4*)s)[i], g_DHi, g_DLo, i);
}
__global__ void k_split_pow() {
    size_t i = (size_t)blockIdx.x * 256 + threadIdx.x;
    if (i < (size_t)17 * 65536 / 4) split4(((const float4*)g_Pow)[i], g_PowHi, g_PowLo, i);
}
__global__ void k_bnd(const float* __restrict__ h0) {
    int idx = blockIdx.x * 256 + threadIdx.x;   // 1024*256
    int c = idx >> 8, s = idx & 255;
    float v = (c < 8) ? h0[s] : g_S3[(size_t)(3840 + s) * 1024 + (c - 8)];
    __nv_bfloat16 h = __float2bfloat16(v);
    g_bndHi[idx] = h;
    g_bndLo[idx] = __float2bfloat16(v - __bfloat162float(h));
}

// ---------------- launch ----------------
extern "C" void kernel_launch(void* const* d_in, const int* in_sizes, int n_in,
                              void* d_out, int out_size) {
    const float* x  = (const float*)d_in[0];
    const float* A  = (const float*)d_in[1];
    const float* Bm = (const float*)d_in[2];
    const float* Cm = (const float*)d_in[3];
    const float* Dm = (const float*)d_in[4];
    const float* h0 = (const float*)d_in[5];
    float* y  = (float*)d_out;
    float* hf = ((size_t)out_size >= Y_ELEMS + (size_t)BATCH * NSTATE)
                    ? y + Y_ELEMS : (float*)0;

    cudaFuncSetAttribute(kHG<PG1>,   cudaFuncAttributeMaxDynamicSharedMemorySize, SMEMSZ);
    cudaFuncSetAttribute(kHG<PTRI>,  cudaFuncAttributeMaxDynamicSharedMemorySize, SMEMSZ);
    cudaFuncSetAttribute(kHG<PCORR>, cudaFuncAttributeMaxDynamicSharedMemorySize, SMEMSZ);
    cudaFuncSetAttribute(kHG<PY>,    cudaFuncAttributeMaxDynamicSharedMemorySize, SMEMSZ);

    k_pow_init<<<256, 256>>>(A);
    k_split_x<<<MROWS * DMODEL / 4 / 256, 256>>>(x);
    k_split_B<<<NSTATE * DMODEL / 4 / 256, 256>>>(Bm);
    k_split_C<<<DMODEL * NSTATE / 4 / 256, 256>>>(Cm);
    k_split_D<<<DMODEL * DMODEL / 4 / 256, 256>>>(Dm);
    k_powmul<<<dim3(4, 4, 1), 256>>>(1);
    k_powmul<<<dim3(4, 4, 2), 256>>>(2);
    k_powmul<<<dim3(4, 4, 4), 256>>>(4);
    k_powmul<<<dim3(4, 4, 8), 256>>>(8);
    k_split_pow<<<17 * 65536 / 4 / 256, 256>>>();
    kHG<PG1><<<dim3(NSTATE / 128, MROWS / 128), NTHREADS, SMEMSZ>>>(nullptr);
    kHG<PTRI><<<dim3(NCOLS / 128, TRIM / 128), NTHREADS, SMEMSZ>>>(nullptr);
    k_bnd<<<NCOLS * NSTATE / 256, 256>>>(h0);
    kHG<PCORR><<<dim3(NCOLS / 128, TRIM / 128), NTHREADS, SMEMSZ>>>(hf);
    kHG<PY><<<dim3(DMODEL / 128, MROWS / 128), NTHREADS, SMEMSZ>>>(y);
}